// round 1
// baseline (speedup 1.0000x reference)
#include <cuda_runtime.h>

#define B 16
#define H0 720
#define W0 720
#define HP 359
#define WP 359
#define H2 357
#define W2 357
#define H3 355
#define W3 355

__device__ float g_p1[B * 10 * HP * WP];
__device__ float g_p2[B * 16 * H2 * W2];
__device__ float g_p3[B * 32 * H3 * W3];

// ---------------------------------------------------------------------
// Kernel 1: norm + conv1(3->10,3x3) + PReLU + maxpool(2x2)
// ---------------------------------------------------------------------
__global__ __launch_bounds__(128)
void k_conv1_pool(const float* __restrict__ x,
                  const float* __restrict__ w,
                  const float* __restrict__ bias,
                  const float* __restrict__ alpha)
{
    __shared__ float s_w[270];
    __shared__ float s_b[10];
    __shared__ float s_a[10];
    for (int i = threadIdx.x; i < 270; i += blockDim.x) s_w[i] = w[i];
    if (threadIdx.x < 10) { s_b[threadIdx.x] = bias[threadIdx.x]; s_a[threadIdx.x] = alpha[threadIdx.x]; }
    __syncthreads();

    int px = blockIdx.x * blockDim.x + threadIdx.x;
    int py = blockIdx.y;
    int b  = blockIdx.z;
    if (px >= WP) return;

    int iy = 2 * py, ix = 2 * px;
    float win[3][4][4];
#pragma unroll
    for (int ci = 0; ci < 3; ci++) {
        const float* p = x + ((size_t)(b * 3 + ci) * H0 + iy) * W0 + ix;
#pragma unroll
        for (int r = 0; r < 4; r++)
#pragma unroll
            for (int c = 0; c < 4; c++)
                win[ci][r][c] = (p[r * W0 + c] - 127.5f) * 0.0078125f;
    }

    float* outp = g_p1 + ((size_t)(b * 10) * HP + py) * WP + px;
#pragma unroll
    for (int co = 0; co < 10; co++) {
        float wr[27];
#pragma unroll
        for (int i = 0; i < 27; i++) wr[i] = s_w[co * 27 + i];
        float s00 = s_b[co], s01 = s00, s10 = s00, s11 = s00;
#pragma unroll
        for (int ci = 0; ci < 3; ci++)
#pragma unroll
            for (int ky = 0; ky < 3; ky++)
#pragma unroll
                for (int kx = 0; kx < 3; kx++) {
                    float wv = wr[ci * 9 + ky * 3 + kx];
                    s00 += win[ci][ky    ][kx    ] * wv;
                    s01 += win[ci][ky    ][kx + 1] * wv;
                    s10 += win[ci][ky + 1][kx    ] * wv;
                    s11 += win[ci][ky + 1][kx + 1] * wv;
                }
        float a = s_a[co];
        s00 = s00 >= 0.f ? s00 : a * s00;
        s01 = s01 >= 0.f ? s01 : a * s01;
        s10 = s10 >= 0.f ? s10 : a * s10;
        s11 = s11 >= 0.f ? s11 : a * s11;
        outp[(size_t)co * HP * WP] = fmaxf(fmaxf(s00, s01), fmaxf(s10, s11));
    }
}

// ---------------------------------------------------------------------
// Kernel 2: conv2 (10->16,3x3) + PReLU
// ---------------------------------------------------------------------
__global__ __launch_bounds__(96)
void k_conv2(const float* __restrict__ w,
             const float* __restrict__ bias,
             const float* __restrict__ alpha)
{
    __shared__ float s_w[360];
    __shared__ float s_b[4];
    __shared__ float s_a[4];

    int bz = blockIdx.z;
    int b  = bz >> 2;
    int cg = bz & 3;

    for (int i = threadIdx.x; i < 360; i += blockDim.x) {
        int col = i / 90, rest = i % 90;
        s_w[col * 90 + rest] = w[((cg * 4 + col) * 10) * 9 + rest];
    }
    if (threadIdx.x < 4) {
        s_b[threadIdx.x] = bias[cg * 4 + threadIdx.x];
        s_a[threadIdx.x] = alpha[cg * 4 + threadIdx.x];
    }
    __syncthreads();

    int xg = threadIdx.x;
    if (xg >= 90) return;
    int x0 = xg * 4;
    int py = blockIdx.y;

    float acc[4][4];
#pragma unroll
    for (int c = 0; c < 4; c++)
#pragma unroll
        for (int j = 0; j < 4; j++) acc[c][j] = s_b[c];

#pragma unroll
    for (int ci = 0; ci < 10; ci++) {
        const float* p = g_p1 + ((size_t)(b * 10 + ci) * HP + py) * WP;
        float r[3][6];
#pragma unroll
        for (int ky = 0; ky < 3; ky++)
#pragma unroll
            for (int j = 0; j < 6; j++) {
                int col = x0 + j; col = col <= WP - 1 ? col : WP - 1;
                r[ky][j] = p[ky * WP + col];
            }
#pragma unroll
        for (int c = 0; c < 4; c++) {
            const float* wp = s_w + (c * 10 + ci) * 9;
#pragma unroll
            for (int ky = 0; ky < 3; ky++)
#pragma unroll
                for (int kx = 0; kx < 3; kx++) {
                    float wv = wp[ky * 3 + kx];
                    acc[c][0] += r[ky][kx + 0] * wv;
                    acc[c][1] += r[ky][kx + 1] * wv;
                    acc[c][2] += r[ky][kx + 2] * wv;
                    acc[c][3] += r[ky][kx + 3] * wv;
                }
        }
    }

#pragma unroll
    for (int c = 0; c < 4; c++) {
        float a = s_a[c];
        float* op = g_p2 + ((size_t)(b * 16 + cg * 4 + c) * H2 + py) * W2;
#pragma unroll
        for (int j = 0; j < 4; j++) {
            int xx = x0 + j;
            if (xx < W2) {
                float v = acc[c][j];
                op[xx] = v >= 0.f ? v : a * v;
            }
        }
    }
}

// ---------------------------------------------------------------------
// Kernel 3: conv3 (16->32,3x3) + PReLU
// ---------------------------------------------------------------------
__global__ __launch_bounds__(96)
void k_conv3(const float* __restrict__ w,
             const float* __restrict__ bias,
             const float* __restrict__ alpha)
{
    __shared__ float s_w[576];
    __shared__ float s_b[4];
    __shared__ float s_a[4];

    int bz = blockIdx.z;
    int b  = bz >> 3;
    int cg = bz & 7;

    for (int i = threadIdx.x; i < 576; i += blockDim.x) {
        int col = i / 144, rest = i % 144;
        s_w[col * 144 + rest] = w[((cg * 4 + col) * 16) * 9 + rest];
    }
    if (threadIdx.x < 4) {
        s_b[threadIdx.x] = bias[cg * 4 + threadIdx.x];
        s_a[threadIdx.x] = alpha[cg * 4 + threadIdx.x];
    }
    __syncthreads();

    int xg = threadIdx.x;
    if (xg >= 89) return;
    int x0 = xg * 4;
    int py = blockIdx.y;

    float acc[4][4];
#pragma unroll
    for (int c = 0; c < 4; c++)
#pragma unroll
        for (int j = 0; j < 4; j++) acc[c][j] = s_b[c];

#pragma unroll
    for (int ci = 0; ci < 16; ci++) {
        const float* p = g_p2 + ((size_t)(b * 16 + ci) * H2 + py) * W2;
        float r[3][6];
#pragma unroll
        for (int ky = 0; ky < 3; ky++)
#pragma unroll
            for (int j = 0; j < 6; j++) {
                int col = x0 + j; col = col <= W2 - 1 ? col : W2 - 1;
                r[ky][j] = p[ky * W2 + col];
            }
#pragma unroll
        for (int c = 0; c < 4; c++) {
            const float* wp = s_w + (c * 16 + ci) * 9;
#pragma unroll
            for (int ky = 0; ky < 3; ky++)
#pragma unroll
                for (int kx = 0; kx < 3; kx++) {
                    float wv = wp[ky * 3 + kx];
                    acc[c][0] += r[ky][kx + 0] * wv;
                    acc[c][1] += r[ky][kx + 1] * wv;
                    acc[c][2] += r[ky][kx + 2] * wv;
                    acc[c][3] += r[ky][kx + 3] * wv;
                }
        }
    }

#pragma unroll
    for (int c = 0; c < 4; c++) {
        float a = s_a[c];
        float* op = g_p3 + ((size_t)(b * 32 + cg * 4 + c) * H3 + py) * W3;
#pragma unroll
        for (int j = 0; j < 4; j++) {
            int xx = x0 + j;
            if (xx < W3) {
                float v = acc[c][j];
                op[xx] = v >= 0.f ? v : a * v;
            }
        }
    }
}

// ---------------------------------------------------------------------
// Kernel 4: 1x1 heads + softmax -> out = [reg(16,4,355,355), prob(16,2,355,355)]
// ---------------------------------------------------------------------
__global__ __launch_bounds__(128)
void k_heads(const float* __restrict__ w41,
             const float* __restrict__ b41,
             const float* __restrict__ w42,
             const float* __restrict__ b42,
             float* __restrict__ out)
{
    __shared__ float s41[64];
    __shared__ float s42[128];
    __shared__ float sb41[2];
    __shared__ float sb42[4];
    for (int i = threadIdx.x; i < 64; i += blockDim.x) s41[i] = w41[i];
    for (int i = threadIdx.x; i < 128; i += blockDim.x) s42[i] = w42[i];
    if (threadIdx.x < 2) sb41[threadIdx.x] = b41[threadIdx.x];
    if (threadIdx.x < 4) sb42[threadIdx.x] = b42[threadIdx.x];
    __syncthreads();

    int px = blockIdx.x * blockDim.x + threadIdx.x;
    int py = blockIdx.y;
    int b  = blockIdx.z;
    if (px >= W3) return;

    const size_t plane = (size_t)H3 * W3;
    const float* p = g_p3 + ((size_t)(b * 32) * H3 + py) * W3 + px;

    float l0 = sb41[0], l1 = sb41[1];
    float r0 = sb42[0], r1 = sb42[1], r2 = sb42[2], r3 = sb42[3];
#pragma unroll
    for (int ci = 0; ci < 32; ci++) {
        float v = p[(size_t)ci * plane];
        l0 += v * s41[ci];
        l1 += v * s41[32 + ci];
        r0 += v * s42[ci];
        r1 += v * s42[32 + ci];
        r2 += v * s42[64 + ci];
        r3 += v * s42[96 + ci];
    }
    float m = fmaxf(l0, l1);
    float e0 = __expf(l0 - m), e1 = __expf(l1 - m);
    float inv = 1.0f / (e0 + e1);

    size_t pix = (size_t)py * W3 + px;
    const size_t PROB_OFF = (size_t)B * 4 * plane;
    out[((size_t)(b * 4 + 0)) * plane + pix] = r0;
    out[((size_t)(b * 4 + 1)) * plane + pix] = r1;
    out[((size_t)(b * 4 + 2)) * plane + pix] = r2;
    out[((size_t)(b * 4 + 3)) * plane + pix] = r3;
    out[PROB_OFF + ((size_t)(b * 2 + 0)) * plane + pix] = e0 * inv;
    out[PROB_OFF + ((size_t)(b * 2 + 1)) * plane + pix] = e1 * inv;
}

extern "C" void kernel_launch(void* const* d_in, const int* in_sizes, int n_in,
                              void* d_out, int out_size)
{
    const float* x        = (const float*)d_in[0];
    const float* conv1_w  = (const float*)d_in[1];
    const float* conv1_b  = (const float*)d_in[2];
    const float* prelu1_a = (const float*)d_in[3];
    const float* conv2_w  = (const float*)d_in[4];
    const float* conv2_b  = (const float*)d_in[5];
    const float* prelu2_a = (const float*)d_in[6];
    const float* conv3_w  = (const float*)d_in[7];
    const float* conv3_b  = (const float*)d_in[8];
    const float* prelu3_a = (const float*)d_in[9];
    const float* conv41_w = (const float*)d_in[10];
    const float* conv41_b = (const float*)d_in[11];
    const float* conv42_w = (const float*)d_in[12];
    const float* conv42_b = (const float*)d_in[13];
    float* out = (float*)d_out;

    dim3 g1((WP + 127) / 128, HP, B);
    k_conv1_pool<<<g1, 128>>>(x, conv1_w, conv1_b, prelu1_a);

    dim3 g2(1, H2, B * 4);
    k_conv2<<<g2, 96>>>(conv2_w, conv2_b, prelu2_a);

    dim3 g3(1, H3, B * 8);
    k_conv3<<<g3, 96>>>(conv3_w, conv3_b, prelu3_a);

    dim3 g4((W3 + 127) / 128, H3, B);
    k_heads<<<g4, 128>>>(conv41_w, conv41_b, conv42_w, conv42_b, out);
}

// round 3
// speedup vs baseline: 1.2761x; 1.2761x over previous
#include <cuda_runtime.h>

#define B 16
#define H0 720
#define W0 720
#define HP 359
#define WP 359
#define H2 357
#define W2 357
#define H3 355
#define W3 355

__device__ float g_p1[B * 10 * HP * WP];
__device__ float g_p2[B * 16 * H2 * W2];
__device__ float g_p3[B * 32 * H3 * W3];

// ---------------- packed f32x2 helpers ----------------
__device__ __forceinline__ unsigned long long pack2(float a, float b) {
    unsigned long long r;
    asm("mov.b64 %0, {%1,%2};" : "=l"(r) : "f"(a), "f"(b));
    return r;
}
__device__ __forceinline__ void fma2(unsigned long long& d,
                                     unsigned long long a,
                                     unsigned long long b) {
    asm("fma.rn.f32x2 %0, %1, %2, %0;" : "+l"(d) : "l"(a), "l"(b));
}
__device__ __forceinline__ float2 unpack2(unsigned long long v) {
    float2 f;
    asm("mov.b64 {%0,%1}, %2;" : "=f"(f.x), "=f"(f.y) : "l"(v));
    return f;
}

// ---------------------------------------------------------------------
// Kernel 1: norm + conv1(3->10,3x3) + PReLU + maxpool(2x2)   [f32x2]
// one thread per (b, pooled y, pooled x); acc[10 couts][2 row-pairs]
// ---------------------------------------------------------------------
__global__ __launch_bounds__(128)
void k_conv1_pool(const float* __restrict__ x,
                  const float* __restrict__ w,
                  const float* __restrict__ bias,
                  const float* __restrict__ alpha)
{
    __shared__ float s_w[270];
    __shared__ float s_b[10];
    __shared__ float s_a[10];
    for (int i = threadIdx.x; i < 270; i += blockDim.x) s_w[i] = w[i];
    if (threadIdx.x < 10) { s_b[threadIdx.x] = bias[threadIdx.x]; s_a[threadIdx.x] = alpha[threadIdx.x]; }
    __syncthreads();

    int px = blockIdx.x * blockDim.x + threadIdx.x;
    int py = blockIdx.y;
    int b  = blockIdx.z;
    if (px >= WP) return;

    int iy = 2 * py, ix = 2 * px;

    unsigned long long acc[10][2];
#pragma unroll
    for (int co = 0; co < 10; co++) {
        float bb = s_b[co];
        acc[co][0] = pack2(bb, bb);
        acc[co][1] = pack2(bb, bb);
    }

#pragma unroll
    for (int ci = 0; ci < 3; ci++) {
        const float* p = x + ((size_t)(b * 3 + ci) * H0 + iy) * W0 + ix;
        unsigned long long wpair[4][3];  // row r, pair (kx,kx+1)
#pragma unroll
        for (int r = 0; r < 4; r++) {
            float v0 = (p[r * W0 + 0] - 127.5f) * 0.0078125f;
            float v1 = (p[r * W0 + 1] - 127.5f) * 0.0078125f;
            float v2 = (p[r * W0 + 2] - 127.5f) * 0.0078125f;
            float v3 = (p[r * W0 + 3] - 127.5f) * 0.0078125f;
            wpair[r][0] = pack2(v0, v1);
            wpair[r][1] = pack2(v1, v2);
            wpair[r][2] = pack2(v2, v3);
        }
#pragma unroll
        for (int co = 0; co < 10; co++) {
            const float* wp = s_w + co * 27 + ci * 9;
#pragma unroll
            for (int ky = 0; ky < 3; ky++)
#pragma unroll
                for (int kx = 0; kx < 3; kx++) {
                    float wv = wp[ky * 3 + kx];
                    unsigned long long wd = pack2(wv, wv);
                    fma2(acc[co][0], wpair[ky    ][kx], wd);  // rows iy+ky   -> (s00,s01)
                    fma2(acc[co][1], wpair[ky + 1][kx], wd);  // rows iy+ky+1 -> (s10,s11)
                }
        }
    }

    float* outp = g_p1 + ((size_t)(b * 10) * HP + py) * WP + px;
#pragma unroll
    for (int co = 0; co < 10; co++) {
        float a = s_a[co];
        float2 t = unpack2(acc[co][0]);
        float2 u = unpack2(acc[co][1]);
        float s00 = t.x >= 0.f ? t.x : a * t.x;
        float s01 = t.y >= 0.f ? t.y : a * t.y;
        float s10 = u.x >= 0.f ? u.x : a * u.x;
        float s11 = u.y >= 0.f ? u.y : a * u.y;
        outp[(size_t)co * HP * WP] = fmaxf(fmaxf(s00, s01), fmaxf(s10, s11));
    }
}

// ---------------------------------------------------------------------
// Kernel 2: conv2 (10->16,3x3) + PReLU   [f32x2, 8 couts/thread, 4 x]
// grid: y=H2, z=B*2
// ---------------------------------------------------------------------
__global__ __launch_bounds__(96)
void k_conv2(const float* __restrict__ w,
             const float* __restrict__ bias,
             const float* __restrict__ alpha)
{
    __shared__ float s_w[8 * 90];
    __shared__ float s_b[8];
    __shared__ float s_a[8];

    int bz = blockIdx.z;
    int b  = bz >> 1;
    int cg = bz & 1;   // 8-cout group

    for (int i = threadIdx.x; i < 720; i += blockDim.x) {
        int col = i / 90, rest = i % 90;
        s_w[col * 90 + rest] = w[((cg * 8 + col) * 10) * 9 + rest];
    }
    if (threadIdx.x < 8) {
        s_b[threadIdx.x] = bias[cg * 8 + threadIdx.x];
        s_a[threadIdx.x] = alpha[cg * 8 + threadIdx.x];
    }
    __syncthreads();

    int xg = threadIdx.x;
    if (xg >= 90) return;
    int x0 = xg * 4;
    int py = blockIdx.y;

    unsigned long long acc[8][2];
#pragma unroll
    for (int c = 0; c < 8; c++) {
        float bb = s_b[c];
        acc[c][0] = pack2(bb, bb);
        acc[c][1] = pack2(bb, bb);
    }

#pragma unroll
    for (int ci = 0; ci < 10; ci++) {
        const float* p = g_p1 + ((size_t)(b * 10 + ci) * HP + py) * WP;
        unsigned long long pr[3][5];
#pragma unroll
        for (int ky = 0; ky < 3; ky++) {
            float r[6];
#pragma unroll
            for (int j = 0; j < 6; j++) {
                int col = x0 + j; col = col <= WP - 1 ? col : WP - 1;
                r[j] = p[ky * WP + col];
            }
            pr[ky][0] = pack2(r[0], r[1]);
            pr[ky][1] = pack2(r[1], r[2]);
            pr[ky][2] = pack2(r[2], r[3]);
            pr[ky][3] = pack2(r[3], r[4]);
            pr[ky][4] = pack2(r[4], r[5]);
        }
#pragma unroll
        for (int c = 0; c < 8; c++) {
            const float* wp = s_w + c * 90 + ci * 9;
#pragma unroll
            for (int ky = 0; ky < 3; ky++)
#pragma unroll
                for (int kx = 0; kx < 3; kx++) {
                    float wv = wp[ky * 3 + kx];
                    unsigned long long wd = pack2(wv, wv);
                    fma2(acc[c][0], pr[ky][kx    ], wd);  // x0, x0+1
                    fma2(acc[c][1], pr[ky][kx + 2], wd);  // x0+2, x0+3
                }
        }
    }

#pragma unroll
    for (int c = 0; c < 8; c++) {
        float a = s_a[c];
        float* op = g_p2 + ((size_t)(b * 16 + cg * 8 + c) * H2 + py) * W2;
        float2 t = unpack2(acc[c][0]);
        float2 u = unpack2(acc[c][1]);
        float v[4] = {t.x, t.y, u.x, u.y};
#pragma unroll
        for (int j = 0; j < 4; j++) {
            int xx = x0 + j;
            if (xx < W2) {
                float vv = v[j];
                op[xx] = vv >= 0.f ? vv : a * vv;
            }
        }
    }
}

// ---------------------------------------------------------------------
// Kernel 3: conv3 (16->32,3x3) + PReLU   [f32x2, 8 couts/thread, 4 x]
// grid: y=H3, z=B*4
// ---------------------------------------------------------------------
__global__ __launch_bounds__(96)
void k_conv3(const float* __restrict__ w,
             const float* __restrict__ bias,
             const float* __restrict__ alpha)
{
    __shared__ float s_w[8 * 144];
    __shared__ float s_b[8];
    __shared__ float s_a[8];

    int bz = blockIdx.z;
    int b  = bz >> 2;
    int cg = bz & 3;   // 8-cout group

    for (int i = threadIdx.x; i < 1152; i += blockDim.x) {
        int col = i / 144, rest = i % 144;
        s_w[col * 144 + rest] = w[((cg * 8 + col) * 16) * 9 + rest];
    }
    if (threadIdx.x < 8) {
        s_b[threadIdx.x] = bias[cg * 8 + threadIdx.x];
        s_a[threadIdx.x] = alpha[cg * 8 + threadIdx.x];
    }
    __syncthreads();

    int xg = threadIdx.x;
    if (xg >= 89) return;
    int x0 = xg * 4;
    int py = blockIdx.y;

    unsigned long long acc[8][2];
#pragma unroll
    for (int c = 0; c < 8; c++) {
        float bb = s_b[c];
        acc[c][0] = pack2(bb, bb);
        acc[c][1] = pack2(bb, bb);
    }

#pragma unroll
    for (int ci = 0; ci < 16; ci++) {
        const float* p = g_p2 + ((size_t)(b * 16 + ci) * H2 + py) * W2;
        unsigned long long pr[3][5];
#pragma unroll
        for (int ky = 0; ky < 3; ky++) {
            float r[6];
#pragma unroll
            for (int j = 0; j < 6; j++) {
                int col = x0 + j; col = col <= W2 - 1 ? col : W2 - 1;
                r[j] = p[ky * W2 + col];
            }
            pr[ky][0] = pack2(r[0], r[1]);
            pr[ky][1] = pack2(r[1], r[2]);
            pr[ky][2] = pack2(r[2], r[3]);
            pr[ky][3] = pack2(r[3], r[4]);
            pr[ky][4] = pack2(r[4], r[5]);
        }
#pragma unroll
        for (int c = 0; c < 8; c++) {
            const float* wp = s_w + c * 144 + ci * 9;
#pragma unroll
            for (int ky = 0; ky < 3; ky++)
#pragma unroll
                for (int kx = 0; kx < 3; kx++) {
                    float wv = wp[ky * 3 + kx];
                    unsigned long long wd = pack2(wv, wv);
                    fma2(acc[c][0], pr[ky][kx    ], wd);
                    fma2(acc[c][1], pr[ky][kx + 2], wd);
                }
        }
    }

#pragma unroll
    for (int c = 0; c < 8; c++) {
        float a = s_a[c];
        float* op = g_p3 + ((size_t)(b * 32 + cg * 8 + c) * H3 + py) * W3;
        float2 t = unpack2(acc[c][0]);
        float2 u = unpack2(acc[c][1]);
        float v[4] = {t.x, t.y, u.x, u.y};
#pragma unroll
        for (int j = 0; j < 4; j++) {
            int xx = x0 + j;
            if (xx < W3) {
                float vv = v[j];
                op[xx] = vv >= 0.f ? vv : a * vv;
            }
        }
    }
}

// ---------------------------------------------------------------------
// Kernel 4: 1x1 heads + softmax -> out = [reg(16,4,355,355), prob(16,2,355,355)]
// ---------------------------------------------------------------------
__global__ __launch_bounds__(128)
void k_heads(const float* __restrict__ w41,
             const float* __restrict__ b41,
             const float* __restrict__ w42,
             const float* __restrict__ b42,
             float* __restrict__ out)
{
    __shared__ float s41[64];
    __shared__ float s42[128];
    __shared__ float sb41[2];
    __shared__ float sb42[4];
    for (int i = threadIdx.x; i < 64; i += blockDim.x) s41[i] = w41[i];
    for (int i = threadIdx.x; i < 128; i += blockDim.x) s42[i] = w42[i];
    if (threadIdx.x < 2) sb41[threadIdx.x] = b41[threadIdx.x];
    if (threadIdx.x < 4) sb42[threadIdx.x] = b42[threadIdx.x];
    __syncthreads();

    int px = blockIdx.x * blockDim.x + threadIdx.x;
    int py = blockIdx.y;
    int b  = blockIdx.z;
    if (px >= W3) return;

    const size_t plane = (size_t)H3 * W3;
    const float* p = g_p3 + ((size_t)(b * 32) * H3 + py) * W3 + px;

    float l0 = sb41[0], l1 = sb41[1];
    float r0 = sb42[0], r1 = sb42[1], r2 = sb42[2], r3 = sb42[3];
#pragma unroll
    for (int ci = 0; ci < 32; ci++) {
        float v = p[(size_t)ci * plane];
        l0 += v * s41[ci];
        l1 += v * s41[32 + ci];
        r0 += v * s42[ci];
        r1 += v * s42[32 + ci];
        r2 += v * s42[64 + ci];
        r3 += v * s42[96 + ci];
    }
    float m = fmaxf(l0, l1);
    float e0 = __expf(l0 - m), e1 = __expf(l1 - m);
    float inv = 1.0f / (e0 + e1);

    size_t pix = (size_t)py * W3 + px;
    const size_t PROB_OFF = (size_t)B * 4 * plane;
    out[((size_t)(b * 4 + 0)) * plane + pix] = r0;
    out[((size_t)(b * 4 + 1)) * plane + pix] = r1;
    out[((size_t)(b * 4 + 2)) * plane + pix] = r2;
    out[((size_t)(b * 4 + 3)) * plane + pix] = r3;
    out[PROB_OFF + ((size_t)(b * 2 + 0)) * plane + pix] = e0 * inv;
    out[PROB_OFF + ((size_t)(b * 2 + 1)) * plane + pix] = e1 * inv;
}

extern "C" void kernel_launch(void* const* d_in, const int* in_sizes, int n_in,
                              void* d_out, int out_size)
{
    const float* x        = (const float*)d_in[0];
    const float* conv1_w  = (const float*)d_in[1];
    const float* conv1_b  = (const float*)d_in[2];
    const float* prelu1_a = (const float*)d_in[3];
    const float* conv2_w  = (const float*)d_in[4];
    const float* conv2_b  = (const float*)d_in[5];
    const float* prelu2_a = (const float*)d_in[6];
    const float* conv3_w  = (const float*)d_in[7];
    const float* conv3_b  = (const float*)d_in[8];
    const float* prelu3_a = (const float*)d_in[9];
    const float* conv41_w = (const float*)d_in[10];
    const float* conv41_b = (const float*)d_in[11];
    const float* conv42_w = (const float*)d_in[12];
    const float* conv42_b = (const float*)d_in[13];
    float* out = (float*)d_out;

    dim3 g1((WP + 127) / 128, HP, B);
    k_conv1_pool<<<g1, 128>>>(x, conv1_w, conv1_b, prelu1_a);

    dim3 g2(1, H2, B * 2);
    k_conv2<<<g2, 96>>>(conv2_w, conv2_b, prelu2_a);

    dim3 g3(1, H3, B * 4);
    k_conv3<<<g3, 96>>>(conv3_w, conv3_b, prelu3_a);

    dim3 g4((W3 + 127) / 128, H3, B);
    k_heads<<<g4, 128>>>(conv41_w, conv41_b, conv42_w, conv42_b, out);
}